// round 3
// baseline (speedup 1.0000x reference)
#include <cuda_runtime.h>
#include <math.h>

#define NB      4
#define D_MODEL 256
#define HEADS   4
#define HEAD_DIM 64
#define NPTS    4096
#define TWO_D   512
#define L2E     1.4426950408889634f

// ---------------- scratch (device globals; no allocations allowed) ----------
__device__ float g_Q[NB * D_MODEL * NPTS];
__device__ float g_K[NB * D_MODEL * NPTS];
__device__ float g_V[NB * D_MODEL * NPTS];
__device__ float g_attn[NB * D_MODEL * NPTS];   // [b][h*64+d][n] layout!
__device__ float g_msg[NB * D_MODEL * NPTS];
__device__ float g_h[NB * TWO_D * NPTS];
__device__ float g_mean[TWO_D];
__device__ float g_istd[TWO_D];

// ---------------------------------------------------------------------------
// helpers
// ---------------------------------------------------------------------------
__device__ __forceinline__ unsigned f2tf32(float f) {
    unsigned u; asm("cvt.rna.tf32.f32 %0, %1;" : "=r"(u) : "f"(f)); return u;
}
__device__ __forceinline__ float ex2(float x) {
    float y; asm("ex2.approx.f32 %0, %1;" : "=f"(y) : "f"(x)); return y;
}
__device__ __forceinline__ void mma_tf32(float c[4],
    unsigned a0, unsigned a1, unsigned a2, unsigned a3,
    unsigned b0, unsigned b1)
{
    asm volatile(
        "mma.sync.aligned.m16n8k8.row.col.f32.tf32.tf32.f32 "
        "{%0,%1,%2,%3},{%4,%5,%6,%7},{%8,%9},{%0,%1,%2,%3};"
        : "+f"(c[0]), "+f"(c[1]), "+f"(c[2]), "+f"(c[3])
        : "r"(a0), "r"(a1), "r"(a2), "r"(a3), "r"(b0), "r"(b1));
}

// ---------------------------------------------------------------------------
// Generic conv1 (1x1 conv == per-position GEMM), fp32 SIMT.
//   perm  : W column index permutation c -> (c&63)*4 + (c>>6)  (merge after
//           attention output stored in [h][d] channel order)
//   cvtout: round outputs to tf32 (rna) for downstream tensor-core consumers
// ---------------------------------------------------------------------------
__global__ void __launch_bounds__(256) gemm_conv1(
    const float* __restrict__ A, const float* __restrict__ B2,
    const float* __restrict__ W, const float* __restrict__ bias,
    float* __restrict__ out, int Ca, int Cb, int O, int perm, int cvtout)
{
    __shared__ float Ws[16][68];
    __shared__ float Xs[16][64];

    const int b  = blockIdx.z;
    const int o0 = blockIdx.y * 64;
    const int n0 = blockIdx.x * 64;
    const int t  = threadIdx.x;
    const int tx = t & 15;
    const int ty = t >> 4;
    const int C  = Ca + Cb;

    const float* Abase = A + (size_t)b * Ca * NPTS + n0;
    const float* Bbase = (Cb > 0) ? (B2 + (size_t)b * Cb * NPTS + n0) : nullptr;

    float acc[4][4];
#pragma unroll
    for (int i = 0; i < 4; i++)
#pragma unroll
        for (int j = 0; j < 4; j++) acc[i][j] = 0.f;

    for (int k0 = 0; k0 < C; k0 += 16) {
#pragma unroll
        for (int r = 0; r < 4; r++) {
            int idx = t + r * 256;
            int kk = idx & 15, oo = idx >> 4;
            int c = k0 + kk;
            if (perm) c = ((c & 63) << 2) | (c >> 6);
            Ws[kk][oo] = W[(size_t)(o0 + oo) * C + c];
        }
#pragma unroll
        for (int r = 0; r < 4; r++) {
            int idx = t + r * 256;
            int nn = idx & 63, kk = idx >> 6;
            int c = k0 + kk;
            float v = (c < Ca) ? Abase[(size_t)c * NPTS + nn]
                               : Bbase[(size_t)(c - Ca) * NPTS + nn];
            Xs[kk][nn] = v;
        }
        __syncthreads();

#pragma unroll
        for (int kk = 0; kk < 16; kk++) {
            float4 a4 = *(const float4*)&Ws[kk][ty * 4];
            float4 b4 = *(const float4*)&Xs[kk][tx * 4];
            float av[4] = {a4.x, a4.y, a4.z, a4.w};
            float bv[4] = {b4.x, b4.y, b4.z, b4.w};
#pragma unroll
            for (int i = 0; i < 4; i++)
#pragma unroll
                for (int j = 0; j < 4; j++) acc[i][j] = fmaf(av[i], bv[j], acc[i][j]);
        }
        __syncthreads();
    }

#pragma unroll
    for (int i = 0; i < 4; i++) {
        float bs = bias[o0 + ty * 4 + i];
        float4 r;
        r.x = acc[i][0] + bs; r.y = acc[i][1] + bs;
        r.z = acc[i][2] + bs; r.w = acc[i][3] + bs;
        if (cvtout) {
            r.x = __uint_as_float(f2tf32(r.x));
            r.y = __uint_as_float(f2tf32(r.y));
            r.z = __uint_as_float(f2tf32(r.z));
            r.w = __uint_as_float(f2tf32(r.w));
        }
        *(float4*)&out[((size_t)b * O + o0 + ty * 4 + i) * NPTS + n0 + tx * 4] = r;
    }
}

// ---------------------------------------------------------------------------
// Flash attention on the tensor pipe: mma.sync m16n8k8 tf32.
// Block = 128 threads (4 warps), 64 q-rows per block, 64-wide kv tiles.
// Warp w owns q rows [w*16, w*16+16). Inputs are tf32-pre-rounded by the
// projection GEMMs. Output written to g_attn in [b][h][d][n] layout
// (coalesced); the d*4+h interleave is folded into the merge GEMM.
// ---------------------------------------------------------------------------
#define QS_STR 68
#define KS_STR 72
#define FA2_SMEM_BYTES ((64 * QS_STR * 2 + 64 * KS_STR * 2) * 4)

extern __shared__ float fa_sm[];

__global__ void __launch_bounds__(128) flash_attn_tf32(
    const float* __restrict__ Q, const float* __restrict__ K,
    const float* __restrict__ V, float* __restrict__ Out)
{
    float* Qs = fa_sm;                 // [n][d], stride 68 (A-frag CF)
    float* Ps = Qs + 64 * QS_STR;      // [n][m] stride 68; epilogue [n][d] stride 65
    float* Ks = Ps + 64 * QS_STR;      // [d][m], stride 72 (B-frag CF)
    float* Vs = Ks + 64 * KS_STR;      // [m][d], stride 72 (B-frag CF)
    unsigned* Qsu = (unsigned*)Qs;
    unsigned* Psu = (unsigned*)Ps;
    unsigned* Ksu = (unsigned*)Ks;
    unsigned* Vsu = (unsigned*)Vs;

    const int n0   = blockIdx.x * 64;
    const int h    = blockIdx.y;
    const int b    = blockIdx.z;
    const int t    = threadIdx.x;
    const int warp = t >> 5;
    const int lane = t & 31;
    const int g    = lane >> 2;    // row group (0..7)
    const int qt   = lane & 3;     // thread-in-group (0..3)
    const int w16  = warp * 16;

    const float* Qb = Q + (size_t)b * D_MODEL * NPTS;
    const float* Kb = K + (size_t)b * D_MODEL * NPTS;
    const float* Vb = V + (size_t)b * D_MODEL * NPTS;

    // ---- load Q tile once: transpose [d][n]->[n][d], fold 1/sqrt(64) (exact pow2)
#pragma unroll
    for (int r = 0; r < 8; r++) {
        int idx = r * 128 + t;
        int dd = idx >> 4, nv = (idx & 15) * 4;
        const float4 q4 = *(const float4*)&Qb[(size_t)(dd * HEADS + h) * NPTS + n0 + nv];
        Qs[(nv + 0) * QS_STR + dd] = q4.x * 0.125f;
        Qs[(nv + 1) * QS_STR + dd] = q4.y * 0.125f;
        Qs[(nv + 2) * QS_STR + dd] = q4.z * 0.125f;
        Qs[(nv + 3) * QS_STR + dd] = q4.w * 0.125f;
    }

    float mr0 = -INFINITY, mr1 = -INFINITY, l0 = 0.f, l1 = 0.f;
    float oacc[8][4];
#pragma unroll
    for (int i = 0; i < 8; i++)
#pragma unroll
        for (int j = 0; j < 4; j++) oacc[i][j] = 0.f;

    for (int m0 = 0; m0 < NPTS; m0 += 64) {
        __syncthreads();   // protect Ks/Vs reuse
        // ---- load K [d][m] (vectorized) and V transposed [m][d]
#pragma unroll
        for (int r = 0; r < 8; r++) {
            int idx = r * 128 + t;
            int dd = idx >> 4, mv = (idx & 15) * 4;
            *(float4*)&Ks[dd * KS_STR + mv] =
                *(const float4*)&Kb[(size_t)(dd * HEADS + h) * NPTS + m0 + mv];
            const float4 v4 = *(const float4*)&Vb[(size_t)(dd * HEADS + h) * NPTS + m0 + mv];
            Vs[(mv + 0) * KS_STR + dd] = v4.x;
            Vs[(mv + 1) * KS_STR + dd] = v4.y;
            Vs[(mv + 2) * KS_STR + dd] = v4.z;
            Vs[(mv + 3) * KS_STR + dd] = v4.w;
        }
        __syncthreads();

        // ---- S = Q K^T   (warp: 16 rows x 64 cols, 8 k-steps)
        float S[8][4];
#pragma unroll
        for (int i = 0; i < 8; i++)
#pragma unroll
            for (int j = 0; j < 4; j++) S[i][j] = 0.f;

#pragma unroll
        for (int k = 0; k < 8; k++) {
            unsigned a0 = Qsu[(w16 + g)     * QS_STR + k * 8 + qt];
            unsigned a1 = Qsu[(w16 + g + 8) * QS_STR + k * 8 + qt];
            unsigned a2 = Qsu[(w16 + g)     * QS_STR + k * 8 + qt + 4];
            unsigned a3 = Qsu[(w16 + g + 8) * QS_STR + k * 8 + qt + 4];
#pragma unroll
            for (int nt = 0; nt < 8; nt++) {
                unsigned b0 = Ksu[(k * 8 + qt)     * KS_STR + nt * 8 + g];
                unsigned b1 = Ksu[(k * 8 + qt + 4) * KS_STR + nt * 8 + g];
                mma_tf32(S[nt], a0, a1, a2, a3, b0, b1);
            }
        }

        // ---- online softmax (thread owns rows w16+g and w16+g+8)
        float rmax0 = -INFINITY, rmax1 = -INFINITY;
#pragma unroll
        for (int nt = 0; nt < 8; nt++) {
            rmax0 = fmaxf(rmax0, fmaxf(S[nt][0], S[nt][1]));
            rmax1 = fmaxf(rmax1, fmaxf(S[nt][2], S[nt][3]));
        }
        rmax0 = fmaxf(rmax0, __shfl_xor_sync(0xffffffffu, rmax0, 1));
        rmax0 = fmaxf(rmax0, __shfl_xor_sync(0xffffffffu, rmax0, 2));
        rmax1 = fmaxf(rmax1, __shfl_xor_sync(0xffffffffu, rmax1, 1));
        rmax1 = fmaxf(rmax1, __shfl_xor_sync(0xffffffffu, rmax1, 2));

        float mn0 = fmaxf(mr0, rmax0), mn1 = fmaxf(mr1, rmax1);
        float al0 = ex2((mr0 - mn0) * L2E);
        float al1 = ex2((mr1 - mn1) * L2E);

        float rs0 = 0.f, rs1 = 0.f;
#pragma unroll
        for (int nt = 0; nt < 8; nt++) {
            S[nt][0] = ex2((S[nt][0] - mn0) * L2E);
            S[nt][1] = ex2((S[nt][1] - mn0) * L2E);
            S[nt][2] = ex2((S[nt][2] - mn1) * L2E);
            S[nt][3] = ex2((S[nt][3] - mn1) * L2E);
            rs0 += S[nt][0] + S[nt][1];
            rs1 += S[nt][2] + S[nt][3];
        }
        rs0 += __shfl_xor_sync(0xffffffffu, rs0, 1);
        rs0 += __shfl_xor_sync(0xffffffffu, rs0, 2);
        rs1 += __shfl_xor_sync(0xffffffffu, rs1, 1);
        rs1 += __shfl_xor_sync(0xffffffffu, rs1, 2);

        l0 = l0 * al0 + rs0;  l1 = l1 * al1 + rs1;
        mr0 = mn0;            mr1 = mn1;
#pragma unroll
        for (int nt = 0; nt < 8; nt++) {
            oacc[nt][0] *= al0; oacc[nt][1] *= al0;
            oacc[nt][2] *= al1; oacc[nt][3] *= al1;
        }

        // ---- stash P (tf32) into warp-private rows of Ps
#pragma unroll
        for (int nt = 0; nt < 8; nt++) {
            Psu[(w16 + g)     * QS_STR + nt * 8 + 2 * qt]     = f2tf32(S[nt][0]);
            Psu[(w16 + g)     * QS_STR + nt * 8 + 2 * qt + 1] = f2tf32(S[nt][1]);
            Psu[(w16 + g + 8) * QS_STR + nt * 8 + 2 * qt]     = f2tf32(S[nt][2]);
            Psu[(w16 + g + 8) * QS_STR + nt * 8 + 2 * qt + 1] = f2tf32(S[nt][3]);
        }
        __syncwarp();

        // ---- O += P V
#pragma unroll
        for (int k = 0; k < 8; k++) {
            unsigned a0 = Psu[(w16 + g)     * QS_STR + k * 8 + qt];
            unsigned a1 = Psu[(w16 + g + 8) * QS_STR + k * 8 + qt];
            unsigned a2 = Psu[(w16 + g)     * QS_STR + k * 8 + qt + 4];
            unsigned a3 = Psu[(w16 + g + 8) * QS_STR + k * 8 + qt + 4];
#pragma unroll
            for (int dt = 0; dt < 8; dt++) {
                unsigned b0 = Vsu[(k * 8 + qt)     * KS_STR + dt * 8 + g];
                unsigned b1 = Vsu[(k * 8 + qt + 4) * KS_STR + dt * 8 + g];
                mma_tf32(oacc[dt], a0, a1, a2, a3, b0, b1);
            }
        }
        __syncwarp();
    }

    // ---- epilogue: normalize, stage through smem (stride 65), coalesced store
    float inv0 = 1.f / l0, inv1 = 1.f / l1;
#pragma unroll
    for (int nt = 0; nt < 8; nt++) {
        Ps[(w16 + g)     * 65 + nt * 8 + 2 * qt]     = oacc[nt][0] * inv0;
        Ps[(w16 + g)     * 65 + nt * 8 + 2 * qt + 1] = oacc[nt][1] * inv0;
        Ps[(w16 + g + 8) * 65 + nt * 8 + 2 * qt]     = oacc[nt][2] * inv1;
        Ps[(w16 + g + 8) * 65 + nt * 8 + 2 * qt + 1] = oacc[nt][3] * inv1;
    }
    __syncthreads();

    float* ob = Out + ((size_t)(b * HEADS + h) * 64) * NPTS + n0;
#pragma unroll
    for (int i = 0; i < 32; i++) {
        int idx = i * 128 + t;
        int d = idx >> 6, nn = idx & 63;
        ob[(size_t)d * NPTS + nn] = Ps[nn * 65 + d];
    }
}

// ---------------------------------------------------------------------------
// BatchNorm (training batch stats, biased var) + ReLU
// ---------------------------------------------------------------------------
__global__ void __launch_bounds__(256) bn_stats_kernel(
    const float* __restrict__ hbuf, float* __restrict__ meanp, float* __restrict__ istdp)
{
    const int c = blockIdx.x;
    float s = 0.f, s2 = 0.f;
    for (int idx = threadIdx.x; idx < NB * NPTS; idx += 256) {
        int b = idx >> 12;
        int n = idx & (NPTS - 1);
        float v = hbuf[((size_t)b * TWO_D + c) * NPTS + n];
        s += v; s2 += v * v;
    }
    __shared__ float sh[256], sh2[256];
    sh[threadIdx.x] = s; sh2[threadIdx.x] = s2;
    __syncthreads();
    for (int st = 128; st > 0; st >>= 1) {
        if (threadIdx.x < st) {
            sh[threadIdx.x]  += sh[threadIdx.x + st];
            sh2[threadIdx.x] += sh2[threadIdx.x + st];
        }
        __syncthreads();
    }
    if (threadIdx.x == 0) {
        const float invn = 1.f / (float)(NB * NPTS);
        float mean = sh[0] * invn;
        float var  = sh2[0] * invn - mean * mean;
        meanp[c] = mean;
        istdp[c] = rsqrtf(var + 1e-5f);
    }
}

__global__ void __launch_bounds__(256) bn_apply_relu_kernel(
    float* __restrict__ hbuf, const float* __restrict__ gamma,
    const float* __restrict__ beta, const float* __restrict__ meanp,
    const float* __restrict__ istdp)
{
    size_t i4 = (size_t)blockIdx.x * 256 + threadIdx.x;
    size_t e  = i4 * 4;
    int c = (int)((e >> 12) & (TWO_D - 1));
    float mu = meanp[c], is = istdp[c], ga = gamma[c], be = beta[c];
    float4 v = ((float4*)hbuf)[i4];
    v.x = fmaxf(fmaf((v.x - mu) * is, ga, be), 0.f);
    v.y = fmaxf(fmaf((v.y - mu) * is, ga, be), 0.f);
    v.z = fmaxf(fmaf((v.z - mu) * is, ga, be), 0.f);
    v.w = fmaxf(fmaf((v.w - mu) * is, ga, be), 0.f);
    ((float4*)hbuf)[i4] = v;
}

// ---------------------------------------------------------------------------
extern "C" void kernel_launch(void* const* d_in, const int* in_sizes, int n_in,
                              void* d_out, int out_size)
{
    (void)in_sizes; (void)n_in; (void)out_size;

    const float* x       = (const float*)d_in[0];
    const float* src     = (const float*)d_in[1];
    const float* pq_w    = (const float*)d_in[2];
    const float* pq_b    = (const float*)d_in[3];
    const float* pk_w    = (const float*)d_in[4];
    const float* pk_b    = (const float*)d_in[5];
    const float* pv_w    = (const float*)d_in[6];
    const float* pv_b    = (const float*)d_in[7];
    const float* merge_w = (const float*)d_in[8];
    const float* merge_b = (const float*)d_in[9];
    const float* mlp1_w  = (const float*)d_in[10];
    const float* mlp1_b  = (const float*)d_in[11];
    const float* bn_g    = (const float*)d_in[12];
    const float* bn_b    = (const float*)d_in[13];
    const float* mlp2_w  = (const float*)d_in[14];
    const float* mlp2_b  = (const float*)d_in[15];
    float* out = (float*)d_out;

    float *Qp, *Kp, *Vp, *Ap, *Mp, *Hp, *meanp, *istdp;
    cudaGetSymbolAddress((void**)&Qp,    g_Q);
    cudaGetSymbolAddress((void**)&Kp,    g_K);
    cudaGetSymbolAddress((void**)&Vp,    g_V);
    cudaGetSymbolAddress((void**)&Ap,    g_attn);
    cudaGetSymbolAddress((void**)&Mp,    g_msg);
    cudaGetSymbolAddress((void**)&Hp,    g_h);
    cudaGetSymbolAddress((void**)&meanp, g_mean);
    cudaGetSymbolAddress((void**)&istdp, g_istd);

    cudaFuncSetAttribute(flash_attn_tf32,
                         cudaFuncAttributeMaxDynamicSharedMemorySize, FA2_SMEM_BYTES);

    dim3 blk(256);

    // Q/K/V projections (outputs tf32-rounded for the tensor-core attention)
    gemm_conv1<<<dim3(NPTS/64, D_MODEL/64, NB), blk>>>(x,   nullptr, pq_w, pq_b, Qp, D_MODEL, 0, D_MODEL, 0, 1);
    gemm_conv1<<<dim3(NPTS/64, D_MODEL/64, NB), blk>>>(src, nullptr, pk_w, pk_b, Kp, D_MODEL, 0, D_MODEL, 0, 1);
    gemm_conv1<<<dim3(NPTS/64, D_MODEL/64, NB), blk>>>(src, nullptr, pv_w, pv_b, Vp, D_MODEL, 0, D_MODEL, 0, 1);

    // multi-head attention on tensor cores (tf32 mma.sync)
    flash_attn_tf32<<<dim3(NPTS/64, HEADS, NB), dim3(128), FA2_SMEM_BYTES>>>(Qp, Kp, Vp, Ap);

    // merge (attn stored [h][d]-channel order -> permuted W columns)
    gemm_conv1<<<dim3(NPTS/64, D_MODEL/64, NB), blk>>>(Ap, nullptr, merge_w, merge_b, Mp, D_MODEL, 0, D_MODEL, 1, 0);

    // mlp1 on concat([x, message])
    gemm_conv1<<<dim3(NPTS/64, TWO_D/64, NB), blk>>>(x, Mp, mlp1_w, mlp1_b, Hp, D_MODEL, D_MODEL, TWO_D, 0, 0);

    // BatchNorm (batch stats) + ReLU
    bn_stats_kernel<<<TWO_D, 256>>>(Hp, meanp, istdp);
    bn_apply_relu_kernel<<<(NB * TWO_D * NPTS / 4) / 256, 256>>>(Hp, bn_g, bn_b, meanp, istdp);

    // mlp2 -> output
    gemm_conv1<<<dim3(NPTS/64, D_MODEL/64, NB), blk>>>(Hp, nullptr, mlp2_w, mlp2_b, out, TWO_D, 0, D_MODEL, 0, 0);
}

// round 4
// speedup vs baseline: 2.5050x; 2.5050x over previous
#include <cuda_runtime.h>
#include <cuda_bf16.h>
#include <math.h>

#define NB      4
#define D_MODEL 256
#define HEADS   4
#define HEAD_DIM 64
#define NPTS    4096
#define TWO_D   512
#define L2E     1.4426950408889634f

// ---------------- scratch (device globals; no allocations allowed) ----------
__device__ float g_Q[NB * D_MODEL * NPTS];
__device__ float g_K[NB * D_MODEL * NPTS];
__device__ float g_V[NB * D_MODEL * NPTS];
__device__ float g_attn[NB * D_MODEL * NPTS];   // [b][h*64+d][n] layout
__device__ float g_msg[NB * D_MODEL * NPTS];
__device__ float g_h[NB * TWO_D * NPTS];
__device__ float g_mean[TWO_D];
__device__ float g_istd[TWO_D];

// ---------------------------------------------------------------------------
// helpers
// ---------------------------------------------------------------------------
__device__ __forceinline__ float ex2(float x) {
    float y; asm("ex2.approx.f32 %0, %1;" : "=f"(y) : "f"(x)); return y;
}
__device__ __forceinline__ unsigned packbf(float a, float b) {
    __nv_bfloat162 h = __floats2bfloat162_rn(a, b);
    return *(unsigned*)&h;
}
__device__ __forceinline__ void mma_bf16(float c[4],
    unsigned a0, unsigned a1, unsigned a2, unsigned a3,
    unsigned b0, unsigned b1)
{
    asm volatile(
        "mma.sync.aligned.m16n8k16.row.col.f32.bf16.bf16.f32 "
        "{%0,%1,%2,%3},{%4,%5,%6,%7},{%8,%9},{%0,%1,%2,%3};"
        : "+f"(c[0]), "+f"(c[1]), "+f"(c[2]), "+f"(c[3])
        : "r"(a0), "r"(a1), "r"(a2), "r"(a3), "r"(b0), "r"(b1));
}
__device__ __forceinline__ void ldsm_x4(
    unsigned &r0, unsigned &r1, unsigned &r2, unsigned &r3, unsigned addr)
{
    asm volatile("ldmatrix.sync.aligned.m8n8.x4.shared.b16 {%0,%1,%2,%3},[%4];"
        : "=r"(r0), "=r"(r1), "=r"(r2), "=r"(r3) : "r"(addr));
}
__device__ __forceinline__ void ldsm_x4_t(
    unsigned &r0, unsigned &r1, unsigned &r2, unsigned &r3, unsigned addr)
{
    asm volatile("ldmatrix.sync.aligned.m8n8.x4.trans.shared.b16 {%0,%1,%2,%3},[%4];"
        : "=r"(r0), "=r"(r1), "=r"(r2), "=r"(r3) : "r"(addr));
}

// ---------------------------------------------------------------------------
// Generic conv1 (1x1 conv == per-position GEMM), fp32 SIMT.
// ---------------------------------------------------------------------------
__global__ void __launch_bounds__(256) gemm_conv1(
    const float* __restrict__ A, const float* __restrict__ B2,
    const float* __restrict__ W, const float* __restrict__ bias,
    float* __restrict__ out, int Ca, int Cb, int O, int perm)
{
    __shared__ float Ws[16][68];
    __shared__ float Xs[16][64];

    const int b  = blockIdx.z;
    const int o0 = blockIdx.y * 64;
    const int n0 = blockIdx.x * 64;
    const int t  = threadIdx.x;
    const int tx = t & 15;
    const int ty = t >> 4;
    const int C  = Ca + Cb;

    const float* Abase = A + (size_t)b * Ca * NPTS + n0;
    const float* Bbase = (Cb > 0) ? (B2 + (size_t)b * Cb * NPTS + n0) : nullptr;

    float acc[4][4];
#pragma unroll
    for (int i = 0; i < 4; i++)
#pragma unroll
        for (int j = 0; j < 4; j++) acc[i][j] = 0.f;

    for (int k0 = 0; k0 < C; k0 += 16) {
#pragma unroll
        for (int r = 0; r < 4; r++) {
            int idx = t + r * 256;
            int kk = idx & 15, oo = idx >> 4;
            int c = k0 + kk;
            if (perm) c = ((c & 63) << 2) | (c >> 6);
            Ws[kk][oo] = W[(size_t)(o0 + oo) * C + c];
        }
#pragma unroll
        for (int r = 0; r < 4; r++) {
            int idx = t + r * 256;
            int nn = idx & 63, kk = idx >> 6;
            int c = k0 + kk;
            float v = (c < Ca) ? Abase[(size_t)c * NPTS + nn]
                               : Bbase[(size_t)(c - Ca) * NPTS + nn];
            Xs[kk][nn] = v;
        }
        __syncthreads();

#pragma unroll
        for (int kk = 0; kk < 16; kk++) {
            float4 a4 = *(const float4*)&Ws[kk][ty * 4];
            float4 b4 = *(const float4*)&Xs[kk][tx * 4];
            float av[4] = {a4.x, a4.y, a4.z, a4.w};
            float bv[4] = {b4.x, b4.y, b4.z, b4.w};
#pragma unroll
            for (int i = 0; i < 4; i++)
#pragma unroll
                for (int j = 0; j < 4; j++) acc[i][j] = fmaf(av[i], bv[j], acc[i][j]);
        }
        __syncthreads();
    }

#pragma unroll
    for (int i = 0; i < 4; i++) {
        float bs = bias[o0 + ty * 4 + i];
        float4 r;
        r.x = acc[i][0] + bs; r.y = acc[i][1] + bs;
        r.z = acc[i][2] + bs; r.w = acc[i][3] + bs;
        *(float4*)&out[((size_t)b * O + o0 + ty * 4 + i) * NPTS + n0 + tx * 4] = r;
    }
}

// ---------------------------------------------------------------------------
// Flash attention, bf16 mma.m16n8k16 + ldmatrix. 256 threads = 8 warps.
// Block: 128 q rows (16/warp). KV tile: 64. K,V kept in natural [d][m] smem
// layout (no transpose): S-phase B-frag via ldmatrix.trans, PV B-frag via
// plain ldmatrix. Q A-frags loaded once (ldmatrix.trans from [d][q]) and kept
// in registers. P stays in registers (C-frag == A-frag layout).
// log2(e) folded into Q scale -> softmax uses raw ex2.
// ---------------------------------------------------------------------------
#define QSTR 136            // [d][q] stride (bf16), 272B rows: +4 banks/row
#define KSTR 72             // [d][m] stride (bf16), 144B rows: +4 banks/row
#define Q_BYTES  (64 * QSTR * 2)             // 17408
#define KV_BYTES (64 * KSTR * 2)             // 9216
#define FA_SM_BYTES (Q_BYTES + 2 * KV_BYTES) // 35840 (>= 128*65*4 stage)

__global__ void __launch_bounds__(256, 2) flash_attn_bf16(
    const float* __restrict__ Q, const float* __restrict__ K,
    const float* __restrict__ V, float* __restrict__ Out)
{
    __shared__ __align__(16) char sm[FA_SM_BYTES];
    __nv_bfloat16* Qs = (__nv_bfloat16*)sm;                       // [64 d][128 q]
    __nv_bfloat16* Ks = (__nv_bfloat16*)(sm + Q_BYTES);           // [64 d][64 m]
    __nv_bfloat16* Vs = (__nv_bfloat16*)(sm + Q_BYTES + KV_BYTES);// [64 d][64 m]
    float* stage = (float*)sm;                                    // [128][65]

    const int n0   = blockIdx.x * 128;
    const int h    = blockIdx.y;
    const int b    = blockIdx.z;
    const int t    = threadIdx.x;
    const int warp = t >> 5;
    const int lane = t & 31;
    const int w16  = warp * 16;

    const unsigned qs_u = (unsigned)__cvta_generic_to_shared(Qs);
    const unsigned ks_u = (unsigned)__cvta_generic_to_shared(Ks);
    const unsigned vs_u = (unsigned)__cvta_generic_to_shared(Vs);

    // lane offsets for ldmatrix address patterns
    const int qk_row = (lane & 7) + ((lane >> 4) << 3);       // A(trans)/B(trans)
    const int qk_col = ((lane >> 3) & 1) << 3;
    const int v_row  = (lane & 7) + (((lane >> 3) & 1) << 3); // B(non-trans)
    const int v_col  = (lane >> 4) << 3;

    const float* Qb = Q + (size_t)b * D_MODEL * NPTS;
    const float* Kb = K + (size_t)b * D_MODEL * NPTS;
    const float* Vb = V + (size_t)b * D_MODEL * NPTS;

    // ---- load Q tile -> Qs[d][q] as bf16, scaled by (1/8)*log2(e)
    const float qscale = 0.125f * L2E;
#pragma unroll
    for (int r = 0; r < 8; r++) {
        int idx = r * 256 + t;
        int dd = idx >> 5, qv = (idx & 31) * 4;
        float4 q4 = *(const float4*)&Qb[(size_t)(dd * HEADS + h) * NPTS + n0 + qv];
        uint2 p;
        p.x = packbf(q4.x * qscale, q4.y * qscale);
        p.y = packbf(q4.z * qscale, q4.w * qscale);
        *(uint2*)&Qs[dd * QSTR + qv] = p;
    }
    __syncthreads();

    // ---- Q A-frags: 4 k-steps x 4 regs, resident for whole kernel
    unsigned qf[4][4];
#pragma unroll
    for (int kd = 0; kd < 4; kd++) {
        unsigned addr = qs_u + ((kd * 16 + qk_row) * QSTR + w16 + qk_col) * 2;
        ldsm_x4_t(qf[kd][0], qf[kd][1], qf[kd][2], qf[kd][3], addr);
    }

    float mr0 = -INFINITY, mr1 = -INFINITY, l0 = 0.f, l1 = 0.f;
    float O_[8][4];
#pragma unroll
    for (int i = 0; i < 8; i++)
#pragma unroll
        for (int j = 0; j < 4; j++) O_[i][j] = 0.f;

    for (int m0 = 0; m0 < NPTS; m0 += 64) {
        __syncthreads();   // previous tile's mma reads done
        // ---- load K,V tiles: natural [d][m], coalesced, no transpose
#pragma unroll
        for (int r = 0; r < 4; r++) {
            int idx = r * 256 + t;
            int dd = idx >> 4, mv = (idx & 15) * 4;
            size_t go = (size_t)(dd * HEADS + h) * NPTS + m0 + mv;
            float4 k4 = *(const float4*)&Kb[go];
            float4 v4 = *(const float4*)&Vb[go];
            uint2 pk, pv;
            pk.x = packbf(k4.x, k4.y); pk.y = packbf(k4.z, k4.w);
            pv.x = packbf(v4.x, v4.y); pv.y = packbf(v4.z, v4.w);
            *(uint2*)&Ks[dd * KSTR + mv] = pk;
            *(uint2*)&Vs[dd * KSTR + mv] = pv;
        }
        __syncthreads();

        // ---- S = Q K^T : 16 q rows x 64 m, in log2 units
        float S[8][4];
#pragma unroll
        for (int i = 0; i < 8; i++)
#pragma unroll
            for (int j = 0; j < 4; j++) S[i][j] = 0.f;

#pragma unroll
        for (int kd = 0; kd < 4; kd++) {
#pragma unroll
            for (int np = 0; np < 4; np++) {
                unsigned b0, b1, b2, b3;
                unsigned addr = ks_u + ((kd * 16 + qk_row) * KSTR + np * 16 + qk_col) * 2;
                ldsm_x4_t(b0, b1, b2, b3, addr);
                mma_bf16(S[2 * np],     qf[kd][0], qf[kd][1], qf[kd][2], qf[kd][3], b0, b2);
                mma_bf16(S[2 * np + 1], qf[kd][0], qf[kd][1], qf[kd][2], qf[kd][3], b1, b3);
            }
        }

        // ---- online softmax (rows w16+g and w16+g+8; reduce over qt lanes)
        float rmax0 = -INFINITY, rmax1 = -INFINITY;
#pragma unroll
        for (int nt = 0; nt < 8; nt++) {
            rmax0 = fmaxf(rmax0, fmaxf(S[nt][0], S[nt][1]));
            rmax1 = fmaxf(rmax1, fmaxf(S[nt][2], S[nt][3]));
        }
        rmax0 = fmaxf(rmax0, __shfl_xor_sync(0xffffffffu, rmax0, 1));
        rmax0 = fmaxf(rmax0, __shfl_xor_sync(0xffffffffu, rmax0, 2));
        rmax1 = fmaxf(rmax1, __shfl_xor_sync(0xffffffffu, rmax1, 1));
        rmax1 = fmaxf(rmax1, __shfl_xor_sync(0xffffffffu, rmax1, 2));

        float mn0 = fmaxf(mr0, rmax0), mn1 = fmaxf(mr1, rmax1);
        float al0 = ex2(mr0 - mn0);
        float al1 = ex2(mr1 - mn1);

        float rs0 = 0.f, rs1 = 0.f;
#pragma unroll
        for (int nt = 0; nt < 8; nt++) {
            S[nt][0] = ex2(S[nt][0] - mn0);
            S[nt][1] = ex2(S[nt][1] - mn0);
            S[nt][2] = ex2(S[nt][2] - mn1);
            S[nt][3] = ex2(S[nt][3] - mn1);
            rs0 += S[nt][0] + S[nt][1];
            rs1 += S[nt][2] + S[nt][3];
        }
        rs0 += __shfl_xor_sync(0xffffffffu, rs0, 1);
        rs0 += __shfl_xor_sync(0xffffffffu, rs0, 2);
        rs1 += __shfl_xor_sync(0xffffffffu, rs1, 1);
        rs1 += __shfl_xor_sync(0xffffffffu, rs1, 2);

        l0 = l0 * al0 + rs0;  l1 = l1 * al1 + rs1;
        mr0 = mn0;            mr1 = mn1;
#pragma unroll
        for (int nt = 0; nt < 8; nt++) {
            O_[nt][0] *= al0; O_[nt][1] *= al0;
            O_[nt][2] *= al1; O_[nt][3] *= al1;
        }

        // ---- P -> A-frags in registers (C-frag layout == A-frag layout)
        unsigned pf[4][4];
#pragma unroll
        for (int ks = 0; ks < 4; ks++) {
            pf[ks][0] = packbf(S[2 * ks][0],     S[2 * ks][1]);
            pf[ks][1] = packbf(S[2 * ks][2],     S[2 * ks][3]);
            pf[ks][2] = packbf(S[2 * ks + 1][0], S[2 * ks + 1][1]);
            pf[ks][3] = packbf(S[2 * ks + 1][2], S[2 * ks + 1][3]);
        }

        // ---- O += P V
#pragma unroll
        for (int ks = 0; ks < 4; ks++) {
#pragma unroll
            for (int dp = 0; dp < 4; dp++) {
                unsigned b0, b1, b2, b3;
                unsigned addr = vs_u + ((dp * 16 + v_row) * KSTR + ks * 16 + v_col) * 2;
                ldsm_x4(b0, b1, b2, b3, addr);
                mma_bf16(O_[2 * dp],     pf[ks][0], pf[ks][1], pf[ks][2], pf[ks][3], b0, b2);
                mma_bf16(O_[2 * dp + 1], pf[ks][0], pf[ks][1], pf[ks][2], pf[ks][3], b1, b3);
            }
        }
    }

    // ---- epilogue: normalize -> stage [n][d] (stride 65) -> coalesced store
    __syncthreads();    // last tile's smem reads done; stage overlays Qs/Ks/Vs
    const int g = lane >> 2, qt = lane & 3;
    float inv0 = 1.f / l0, inv1 = 1.f / l1;
#pragma unroll
    for (int dt = 0; dt < 8; dt++) {
        stage[(w16 + g)     * 65 + dt * 8 + 2 * qt]     = O_[dt][0] * inv0;
        stage[(w16 + g)     * 65 + dt * 8 + 2 * qt + 1] = O_[dt][1] * inv0;
        stage[(w16 + g + 8) * 65 + dt * 8 + 2 * qt]     = O_[dt][2] * inv1;
        stage[(w16 + g + 8) * 65 + dt * 8 + 2 * qt + 1] = O_[dt][3] * inv1;
    }
    __syncthreads();

    float* ob = Out + ((size_t)(b * HEADS + h) * HEAD_DIM) * NPTS + n0;
#pragma unroll
    for (int r = 0; r < 32; r++) {
        int idx = r * 256 + t;
        int d = idx >> 7, nn = idx & 127;
        ob[(size_t)d * NPTS + nn] = stage[nn * 65 + d];
    }
}

// ---------------------------------------------------------------------------
// BatchNorm (training batch stats, biased var) + ReLU
// ---------------------------------------------------------------------------
__global__ void __launch_bounds__(256) bn_stats_kernel(
    const float* __restrict__ hbuf, float* __restrict__ meanp, float* __restrict__ istdp)
{
    const int c = blockIdx.x;
    float s = 0.f, s2 = 0.f;
    for (int idx = threadIdx.x; idx < NB * NPTS; idx += 256) {
        int b = idx >> 12;
        int n = idx & (NPTS - 1);
        float v = hbuf[((size_t)b * TWO_D + c) * NPTS + n];
        s += v; s2 += v * v;
    }
    __shared__ float sh[256], sh2[256];
    sh[threadIdx.x] = s; sh2[threadIdx.x] = s2;
    __syncthreads();
    for (int st = 128; st > 0; st >>= 1) {
        if (threadIdx.x < st) {
            sh[threadIdx.x]  += sh[threadIdx.x + st];
            sh2[threadIdx.x] += sh2[threadIdx.x + st];
        }
        __syncthreads();
    }
    if (threadIdx.x == 0) {
        const float invn = 1.f / (float)(NB * NPTS);
        float mean = sh[0] * invn;
        float var  = sh2[0] * invn - mean * mean;
        meanp[c] = mean;
        istdp[c] = rsqrtf(var + 1e-5f);
    }
}

__global__ void __launch_bounds__(256) bn_apply_relu_kernel(
    float* __restrict__ hbuf, const float* __restrict__ gamma,
    const float* __restrict__ beta, const float* __restrict__ meanp,
    const float* __restrict__ istdp)
{
    size_t i4 = (size_t)blockIdx.x * 256 + threadIdx.x;
    size_t e  = i4 * 4;
    int c = (int)((e >> 12) & (TWO_D - 1));
    float mu = meanp[c], is = istdp[c], ga = gamma[c], be = beta[c];
    float4 v = ((float4*)hbuf)[i4];
    v.x = fmaxf(fmaf((v.x - mu) * is, ga, be), 0.f);
    v.y = fmaxf(fmaf((v.y - mu) * is, ga, be), 0.f);
    v.z = fmaxf(fmaf((v.z - mu) * is, ga, be), 0.f);
    v.w = fmaxf(fmaf((v.w - mu) * is, ga, be), 0.f);
    ((float4*)hbuf)[i4] = v;
}

// ---------------------------------------------------------------------------
extern "C" void kernel_launch(void* const* d_in, const int* in_sizes, int n_in,
                              void* d_out, int out_size)
{
    (void)in_sizes; (void)n_in; (void)out_size;

    const float* x       = (const float*)d_in[0];
    const float* src     = (const float*)d_in[1];
    const float* pq_w    = (const float*)d_in[2];
    const float* pq_b    = (const float*)d_in[3];
    const float* pk_w    = (const float*)d_in[4];
    const float* pk_b    = (const float*)d_in[5];
    const float* pv_w    = (const float*)d_in[6];
    const float* pv_b    = (const float*)d_in[7];
    const float* merge_w = (const float*)d_in[8];
    const float* merge_b = (const float*)d_in[9];
    const float* mlp1_w  = (const float*)d_in[10];
    const float* mlp1_b  = (const float*)d_in[11];
    const float* bn_g    = (const float*)d_in[12];
    const float* bn_b    = (const float*)d_in[13];
    const float* mlp2_w  = (const float*)d_in[14];
    const float* mlp2_b  = (const float*)d_in[15];
    float* out = (float*)d_out;

    float *Qp, *Kp, *Vp, *Ap, *Mp, *Hp, *meanp, *istdp;
    cudaGetSymbolAddress((void**)&Qp,    g_Q);
    cudaGetSymbolAddress((void**)&Kp,    g_K);
    cudaGetSymbolAddress((void**)&Vp,    g_V);
    cudaGetSymbolAddress((void**)&Ap,    g_attn);
    cudaGetSymbolAddress((void**)&Mp,    g_msg);
    cudaGetSymbolAddress((void**)&Hp,    g_h);
    cudaGetSymbolAddress((void**)&meanp, g_mean);
    cudaGetSymbolAddress((void**)&istdp, g_istd);

    dim3 blk(256);

    // Q/K/V projections (fp32)
    gemm_conv1<<<dim3(NPTS/64, D_MODEL/64, NB), blk>>>(x,   nullptr, pq_w, pq_b, Qp, D_MODEL, 0, D_MODEL, 0);
    gemm_conv1<<<dim3(NPTS/64, D_MODEL/64, NB), blk>>>(src, nullptr, pk_w, pk_b, Kp, D_MODEL, 0, D_MODEL, 0);
    gemm_conv1<<<dim3(NPTS/64, D_MODEL/64, NB), blk>>>(src, nullptr, pv_w, pv_b, Vp, D_MODEL, 0, D_MODEL, 0);

    // multi-head attention: bf16 mma + ldmatrix
    flash_attn_bf16<<<dim3(NPTS/128, HEADS, NB), blk>>>(Qp, Kp, Vp, Ap);

    // merge (attn stored [h][d]-channel order -> permuted W columns)
    gemm_conv1<<<dim3(NPTS/64, D_MODEL/64, NB), blk>>>(Ap, nullptr, merge_w, merge_b, Mp, D_MODEL, 0, D_MODEL, 1);

    // mlp1 on concat([x, message])
    gemm_conv1<<<dim3(NPTS/64, TWO_D/64, NB), blk>>>(x, Mp, mlp1_w, mlp1_b, Hp, D_MODEL, D_MODEL, TWO_D, 0);

    // BatchNorm (batch stats) + ReLU
    bn_stats_kernel<<<TWO_D, 256>>>(Hp, meanp, istdp);
    bn_apply_relu_kernel<<<(NB * TWO_D * NPTS / 4) / 256, 256>>>(Hp, bn_g, bn_b, meanp, istdp);

    // mlp2 -> output
    gemm_conv1<<<dim3(NPTS/64, D_MODEL/64, NB), blk>>>(Hp, nullptr, mlp2_w, mlp2_b, out, TWO_D, 0, D_MODEL, 0);
}

// round 7
// speedup vs baseline: 5.0393x; 2.0117x over previous
#include <cuda_runtime.h>
#include <cuda_bf16.h>
#include <math.h>

#define NB      4
#define D_MODEL 256
#define HEADS   4
#define HEAD_DIM 64
#define NPTS    4096
#define TWO_D   512
#define L2E     1.4426950408889634f

// ---------------- scratch (device globals; no allocations allowed) ----------
__device__ float g_Q[NB * D_MODEL * NPTS];
__device__ float g_K[NB * D_MODEL * NPTS];
__device__ float g_V[NB * D_MODEL * NPTS];
__device__ float g_attn[NB * D_MODEL * NPTS];   // [b][h*64+d][n] layout
__device__ float g_msg[NB * D_MODEL * NPTS];
__device__ float g_h[NB * TWO_D * NPTS];
__device__ float g_scale[TWO_D];
__device__ float g_shift[TWO_D];

// ---------------------------------------------------------------------------
// helpers
// ---------------------------------------------------------------------------
__device__ __forceinline__ float ex2(float x) {
    float y; asm("ex2.approx.f32 %0, %1;" : "=f"(y) : "f"(x)); return y;
}
__device__ __forceinline__ unsigned packbf(float a, float b) {
    __nv_bfloat162 h = __floats2bfloat162_rn(a, b);
    return *(unsigned*)&h;
}
__device__ __forceinline__ float bf_rn(float v) {
    return __bfloat162float(__float2bfloat16_rn(v));
}
__device__ __forceinline__ void mma_bf16(float c[4],
    unsigned a0, unsigned a1, unsigned a2, unsigned a3,
    unsigned b0, unsigned b1)
{
    asm volatile(
        "mma.sync.aligned.m16n8k16.row.col.f32.bf16.bf16.f32 "
        "{%0,%1,%2,%3},{%4,%5,%6,%7},{%8,%9},{%0,%1,%2,%3};"
        : "+f"(c[0]), "+f"(c[1]), "+f"(c[2]), "+f"(c[3])
        : "r"(a0), "r"(a1), "r"(a2), "r"(a3), "r"(b0), "r"(b1));
}
__device__ __forceinline__ void ldsm_x4(
    unsigned &r0, unsigned &r1, unsigned &r2, unsigned &r3, unsigned addr)
{
    asm volatile("ldmatrix.sync.aligned.m8n8.x4.shared.b16 {%0,%1,%2,%3},[%4];"
        : "=r"(r0), "=r"(r1), "=r"(r2), "=r"(r3) : "r"(addr));
}
__device__ __forceinline__ void ldsm_x4_t(
    unsigned &r0, unsigned &r1, unsigned &r2, unsigned &r3, unsigned addr)
{
    asm volatile("ldmatrix.sync.aligned.m8n8.x4.trans.shared.b16 {%0,%1,%2,%3},[%4];"
        : "=r"(r0), "=r"(r1), "=r"(r2), "=r"(r3) : "r"(addr));
}

// ---------------------------------------------------------------------------
// FAST bf16 GEMM (message path): out[b][o][n] = bias[o] + sum_c W[o][c] X[b][c][n]
// 128x128 tile, 256 threads, K-chunk 64. perm: X row for c = (c&3)*64+(c>>2).
// ---------------------------------------------------------------------------
#define WSTR 72
#define XSTR 136

__global__ void __launch_bounds__(256, 2) gemm_bf16(
    const float* __restrict__ A,
    const float* __restrict__ W, const float* __restrict__ bias,
    float* __restrict__ out, int C, int O, int perm)
{
    __shared__ __align__(16) __nv_bfloat16 Ws[128 * WSTR];
    __shared__ __align__(16) __nv_bfloat16 Xs[64 * XSTR];

    const int b  = blockIdx.z;
    const int o0 = blockIdx.y * 128;
    const int n0 = blockIdx.x * 128;
    const int t  = threadIdx.x;
    const int warp = t >> 5;
    const int lane = t & 31;
    const int w_o = (warp & 3) * 32;
    const int w_n = (warp >> 2) * 64;

    const unsigned ws_u = (unsigned)__cvta_generic_to_shared(Ws);
    const unsigned xs_u = (unsigned)__cvta_generic_to_shared(Xs);

    const int a_row  = lane & 15;
    const int a_col  = (lane >> 4) << 3;
    const int bt_row = (lane & 7) + ((lane >> 4) << 3);
    const int bt_col = ((lane >> 3) & 1) << 3;

    float acc[2][8][4];
#pragma unroll
    for (int mt = 0; mt < 2; mt++)
#pragma unroll
        for (int nt = 0; nt < 8; nt++)
#pragma unroll
            for (int j = 0; j < 4; j++) acc[mt][nt][j] = 0.f;

    for (int k0 = 0; k0 < C; k0 += 64) {
#pragma unroll
        for (int r = 0; r < 8; r++) {
            int idx = r * 256 + t;
            int oo = idx >> 4, kv = (idx & 15) * 4;
            float4 w4 = *(const float4*)&W[(size_t)(o0 + oo) * C + k0 + kv];
            uint2 p; p.x = packbf(w4.x, w4.y); p.y = packbf(w4.z, w4.w);
            *(uint2*)&Ws[oo * WSTR + kv] = p;
        }
#pragma unroll
        for (int r = 0; r < 8; r++) {
            int idx = r * 256 + t;
            int kk = idx >> 5, nv = (idx & 31) * 4;
            int c = k0 + kk;
            int row = perm ? ((c & 3) * 64 + (c >> 2)) : c;
            float4 v4 = *(const float4*)&A[((size_t)b * C + row) * NPTS + n0 + nv];
            uint2 p; p.x = packbf(v4.x, v4.y); p.y = packbf(v4.z, v4.w);
            *(uint2*)&Xs[kk * XSTR + nv] = p;
        }
        __syncthreads();

#pragma unroll
        for (int ks = 0; ks < 4; ks++) {
            unsigned a[2][4];
#pragma unroll
            for (int mt = 0; mt < 2; mt++) {
                unsigned addr = ws_u +
                    ((w_o + mt * 16 + a_row) * WSTR + ks * 16 + a_col) * 2;
                ldsm_x4(a[mt][0], a[mt][1], a[mt][2], a[mt][3], addr);
            }
#pragma unroll
            for (int np = 0; np < 4; np++) {
                unsigned b0, b1, b2, b3;
                unsigned addr = xs_u +
                    ((ks * 16 + bt_row) * XSTR + w_n + np * 16 + bt_col) * 2;
                ldsm_x4_t(b0, b1, b2, b3, addr);
#pragma unroll
                for (int mt = 0; mt < 2; mt++) {
                    mma_bf16(acc[mt][2 * np],     a[mt][0], a[mt][1], a[mt][2], a[mt][3], b0, b2);
                    mma_bf16(acc[mt][2 * np + 1], a[mt][0], a[mt][1], a[mt][2], a[mt][3], b1, b3);
                }
            }
        }
        __syncthreads();
    }

    const int g = lane >> 2, qt = lane & 3;
#pragma unroll
    for (int mt = 0; mt < 2; mt++) {
        int row0 = o0 + w_o + mt * 16 + g;
        int row1 = row0 + 8;
        float bs0 = bias[row0], bs1 = bias[row1];
        float* p0 = out + ((size_t)b * O + row0) * NPTS + n0 + w_n + 2 * qt;
        float* p1 = out + ((size_t)b * O + row1) * NPTS + n0 + w_n + 2 * qt;
#pragma unroll
        for (int nt = 0; nt < 8; nt++) {
            float2 v0, v1;
            v0.x = acc[mt][nt][0] + bs0; v0.y = acc[mt][nt][1] + bs0;
            v1.x = acc[mt][nt][2] + bs1; v1.y = acc[mt][nt][3] + bs1;
            *(float2*)&p0[nt * 8] = v0;
            *(float2*)&p1[nt * 8] = v1;
        }
    }
}

// ---------------------------------------------------------------------------
// HIGH-PRECISION split-bf16 GEMM (x path: mlp1, mlp2).
// v = hi + lo (both bf16);  W X ~= Whi Xhi + Whi Xlo + Wlo Xhi  (3 mmas).
// 128x128 tile, 256 threads, K-chunk 32. concat (Ca/Cb) + fused BN-ReLU on X.
// ---------------------------------------------------------------------------
#define SWSTR 40
#define SXSTR 136

__global__ void __launch_bounds__(256, 2) gemm_bf16_hp(
    const float* __restrict__ A, const float* __restrict__ B2,
    const float* __restrict__ W, const float* __restrict__ bias,
    const float* __restrict__ scale, const float* __restrict__ shift,
    float* __restrict__ out, int Ca, int Cb, int O, int bnrelu)
{
    __shared__ __align__(16) __nv_bfloat16 Whi[128 * SWSTR];
    __shared__ __align__(16) __nv_bfloat16 Wlo[128 * SWSTR];
    __shared__ __align__(16) __nv_bfloat16 Xhi[32 * SXSTR];
    __shared__ __align__(16) __nv_bfloat16 Xlo[32 * SXSTR];

    const int b  = blockIdx.z;
    const int o0 = blockIdx.y * 128;
    const int n0 = blockIdx.x * 128;
    const int t  = threadIdx.x;
    const int warp = t >> 5;
    const int lane = t & 31;
    const int w_o = (warp & 3) * 32;
    const int w_n = (warp >> 2) * 64;
    const int C  = Ca + Cb;

    const unsigned whi_u = (unsigned)__cvta_generic_to_shared(Whi);
    const unsigned wlo_u = (unsigned)__cvta_generic_to_shared(Wlo);
    const unsigned xhi_u = (unsigned)__cvta_generic_to_shared(Xhi);
    const unsigned xlo_u = (unsigned)__cvta_generic_to_shared(Xlo);

    const int a_row  = lane & 15;
    const int a_col  = (lane >> 4) << 3;
    const int bt_row = (lane & 7) + ((lane >> 4) << 3);
    const int bt_col = ((lane >> 3) & 1) << 3;

    float acc[2][8][4];
#pragma unroll
    for (int mt = 0; mt < 2; mt++)
#pragma unroll
        for (int nt = 0; nt < 8; nt++)
#pragma unroll
            for (int j = 0; j < 4; j++) acc[mt][nt][j] = 0.f;

    for (int k0 = 0; k0 < C; k0 += 32) {
        // ---- W tile [128 o][32 k], split hi/lo
#pragma unroll
        for (int r = 0; r < 4; r++) {
            int idx = r * 256 + t;
            int oo = idx >> 3, kv = (idx & 7) * 4;
            float4 w4 = *(const float4*)&W[(size_t)(o0 + oo) * C + k0 + kv];
            float hx = bf_rn(w4.x), hy = bf_rn(w4.y), hz = bf_rn(w4.z), hw = bf_rn(w4.w);
            uint2 ph, pl;
            ph.x = packbf(hx, hy); ph.y = packbf(hz, hw);
            pl.x = packbf(w4.x - hx, w4.y - hy);
            pl.y = packbf(w4.z - hz, w4.w - hw);
            *(uint2*)&Whi[oo * SWSTR + kv] = ph;
            *(uint2*)&Wlo[oo * SWSTR + kv] = pl;
        }
        // ---- X tile [32 k][128 n], concat + optional BN-ReLU, split hi/lo
#pragma unroll
        for (int r = 0; r < 4; r++) {
            int idx = r * 256 + t;
            int kk = idx >> 5, nv = (idx & 31) * 4;
            int c = k0 + kk;
            const float* src = (c < Ca) ? (A + ((size_t)b * Ca + c) * NPTS)
                                        : (B2 + ((size_t)b * Cb + (c - Ca)) * NPTS);
            float4 v4 = *(const float4*)&src[n0 + nv];
            if (bnrelu) {
                float sc = scale[c], sh = shift[c];
                v4.x = fmaxf(fmaf(v4.x, sc, sh), 0.f);
                v4.y = fmaxf(fmaf(v4.y, sc, sh), 0.f);
                v4.z = fmaxf(fmaf(v4.z, sc, sh), 0.f);
                v4.w = fmaxf(fmaf(v4.w, sc, sh), 0.f);
            }
            float hx = bf_rn(v4.x), hy = bf_rn(v4.y), hz = bf_rn(v4.z), hw = bf_rn(v4.w);
            uint2 ph, pl;
            ph.x = packbf(hx, hy); ph.y = packbf(hz, hw);
            pl.x = packbf(v4.x - hx, v4.y - hy);
            pl.y = packbf(v4.z - hz, v4.w - hw);
            *(uint2*)&Xhi[kk * SXSTR + nv] = ph;
            *(uint2*)&Xlo[kk * SXSTR + nv] = pl;
        }
        __syncthreads();

#pragma unroll
        for (int ks = 0; ks < 2; ks++) {
            unsigned ah[2][4], al[2][4];
#pragma unroll
            for (int mt = 0; mt < 2; mt++) {
                unsigned off = ((w_o + mt * 16 + a_row) * SWSTR + ks * 16 + a_col) * 2;
                ldsm_x4(ah[mt][0], ah[mt][1], ah[mt][2], ah[mt][3], whi_u + off);
                ldsm_x4(al[mt][0], al[mt][1], al[mt][2], al[mt][3], wlo_u + off);
            }
#pragma unroll
            for (int np = 0; np < 4; np++) {
                unsigned bh0, bh1, bh2, bh3, bl0, bl1, bl2, bl3;
                unsigned off = ((ks * 16 + bt_row) * SXSTR + w_n + np * 16 + bt_col) * 2;
                ldsm_x4_t(bh0, bh1, bh2, bh3, xhi_u + off);
                ldsm_x4_t(bl0, bl1, bl2, bl3, xlo_u + off);
#pragma unroll
                for (int mt = 0; mt < 2; mt++) {
                    // hi*hi
                    mma_bf16(acc[mt][2 * np],     ah[mt][0], ah[mt][1], ah[mt][2], ah[mt][3], bh0, bh2);
                    mma_bf16(acc[mt][2 * np + 1], ah[mt][0], ah[mt][1], ah[mt][2], ah[mt][3], bh1, bh3);
                    // hi*lo
                    mma_bf16(acc[mt][2 * np],     ah[mt][0], ah[mt][1], ah[mt][2], ah[mt][3], bl0, bl2);
                    mma_bf16(acc[mt][2 * np + 1], ah[mt][0], ah[mt][1], ah[mt][2], ah[mt][3], bl1, bl3);
                    // lo*hi
                    mma_bf16(acc[mt][2 * np],     al[mt][0], al[mt][1], al[mt][2], al[mt][3], bh0, bh2);
                    mma_bf16(acc[mt][2 * np + 1], al[mt][0], al[mt][1], al[mt][2], al[mt][3], bh1, bh3);
                }
            }
        }
        __syncthreads();
    }

    const int g = lane >> 2, qt = lane & 3;
#pragma unroll
    for (int mt = 0; mt < 2; mt++) {
        int row0 = o0 + w_o + mt * 16 + g;
        int row1 = row0 + 8;
        float bs0 = bias[row0], bs1 = bias[row1];
        float* p0 = out + ((size_t)b * O + row0) * NPTS + n0 + w_n + 2 * qt;
        float* p1 = out + ((size_t)b * O + row1) * NPTS + n0 + w_n + 2 * qt;
#pragma unroll
        for (int nt = 0; nt < 8; nt++) {
            float2 v0, v1;
            v0.x = acc[mt][nt][0] + bs0; v0.y = acc[mt][nt][1] + bs0;
            v1.x = acc[mt][nt][2] + bs1; v1.y = acc[mt][nt][3] + bs1;
            *(float2*)&p0[nt * 8] = v0;
            *(float2*)&p1[nt * 8] = v1;
        }
    }
}

// ---------------------------------------------------------------------------
// Flash attention, bf16 mma.m16n8k16 + ldmatrix (unchanged, validated).
// ---------------------------------------------------------------------------
#define QSTR 136
#define KSTR 72
#define Q_BYTES  (64 * QSTR * 2)
#define KV_BYTES (64 * KSTR * 2)
#define FA_SM_BYTES (Q_BYTES + 2 * KV_BYTES)

__global__ void __launch_bounds__(256, 2) flash_attn_bf16(
    const float* __restrict__ Q, const float* __restrict__ K,
    const float* __restrict__ V, float* __restrict__ Out)
{
    __shared__ __align__(16) char sm[FA_SM_BYTES];
    __nv_bfloat16* Qs = (__nv_bfloat16*)sm;
    __nv_bfloat16* Ks = (__nv_bfloat16*)(sm + Q_BYTES);
    __nv_bfloat16* Vs = (__nv_bfloat16*)(sm + Q_BYTES + KV_BYTES);
    float* stage = (float*)sm;

    const int n0   = blockIdx.x * 128;
    const int h    = blockIdx.y;
    const int b    = blockIdx.z;
    const int t    = threadIdx.x;
    const int warp = t >> 5;
    const int lane = t & 31;
    const int w16  = warp * 16;

    const unsigned qs_u = (unsigned)__cvta_generic_to_shared(Qs);
    const unsigned ks_u = (unsigned)__cvta_generic_to_shared(Ks);
    const unsigned vs_u = (unsigned)__cvta_generic_to_shared(Vs);

    const int qk_row = (lane & 7) + ((lane >> 4) << 3);
    const int qk_col = ((lane >> 3) & 1) << 3;
    const int v_row  = (lane & 7) + (((lane >> 3) & 1) << 3);
    const int v_col  = (lane >> 4) << 3;

    const float* Qb = Q + (size_t)b * D_MODEL * NPTS;
    const float* Kb = K + (size_t)b * D_MODEL * NPTS;
    const float* Vb = V + (size_t)b * D_MODEL * NPTS;

    const float qscale = 0.125f * L2E;
#pragma unroll
    for (int r = 0; r < 8; r++) {
        int idx = r * 256 + t;
        int dd = idx >> 5, qv = (idx & 31) * 4;
        float4 q4 = *(const float4*)&Qb[(size_t)(dd * HEADS + h) * NPTS + n0 + qv];
        uint2 p;
        p.x = packbf(q4.x * qscale, q4.y * qscale);
        p.y = packbf(q4.z * qscale, q4.w * qscale);
        *(uint2*)&Qs[dd * QSTR + qv] = p;
    }
    __syncthreads();

    unsigned qf[4][4];
#pragma unroll
    for (int kd = 0; kd < 4; kd++) {
        unsigned addr = qs_u + ((kd * 16 + qk_row) * QSTR + w16 + qk_col) * 2;
        ldsm_x4_t(qf[kd][0], qf[kd][1], qf[kd][2], qf[kd][3], addr);
    }

    float mr0 = -INFINITY, mr1 = -INFINITY, l0 = 0.f, l1 = 0.f;
    float O_[8][4];
#pragma unroll
    for (int i = 0; i < 8; i++)
#pragma unroll
        for (int j = 0; j < 4; j++) O_[i][j] = 0.f;

    for (int m0 = 0; m0 < NPTS; m0 += 64) {
        __syncthreads();
#pragma unroll
        for (int r = 0; r < 4; r++) {
            int idx = r * 256 + t;
            int dd = idx >> 4, mv = (idx & 15) * 4;
            size_t go = (size_t)(dd * HEADS + h) * NPTS + m0 + mv;
            float4 k4 = *(const float4*)&Kb[go];
            float4 v4 = *(const float4*)&Vb[go];
            uint2 pk, pv;
            pk.x = packbf(k4.x, k4.y); pk.y = packbf(k4.z, k4.w);
            pv.x = packbf(v4.x, v4.y); pv.y = packbf(v4.z, v4.w);
            *(uint2*)&Ks[dd * KSTR + mv] = pk;
            *(uint2*)&Vs[dd * KSTR + mv] = pv;
        }
        __syncthreads();

        float S[8][4];
#pragma unroll
        for (int i = 0; i < 8; i++)
#pragma unroll
            for (int j = 0; j < 4; j++) S[i][j] = 0.f;

#pragma unroll
        for (int kd = 0; kd < 4; kd++) {
#pragma unroll
            for (int np = 0; np < 4; np++) {
                unsigned b0, b1, b2, b3;
                unsigned addr = ks_u + ((kd * 16 + qk_row) * KSTR + np * 16 + qk_col) * 2;
                ldsm_x4_t(b0, b1, b2, b3, addr);
                mma_bf16(S[2 * np],     qf[kd][0], qf[kd][1], qf[kd][2], qf[kd][3], b0, b2);
                mma_bf16(S[2 * np + 1], qf[kd][0], qf[kd][1], qf[kd][2], qf[kd][3], b1, b3);
            }
        }

        float rmax0 = -INFINITY, rmax1 = -INFINITY;
#pragma unroll
        for (int nt = 0; nt < 8; nt++) {
            rmax0 = fmaxf(rmax0, fmaxf(S[nt][0], S[nt][1]));
            rmax1 = fmaxf(rmax1, fmaxf(S[nt][2], S[nt][3]));
        }
        rmax0 = fmaxf(rmax0, __shfl_xor_sync(0xffffffffu, rmax0, 1));
        rmax0 = fmaxf(rmax0, __shfl_xor_sync(0xffffffffu, rmax0, 2));
        rmax1 = fmaxf(rmax1, __shfl_xor_sync(0xffffffffu, rmax1, 1));
        rmax1 = fmaxf(rmax1, __shfl_xor_sync(0xffffffffu, rmax1, 2));

        float mn0 = fmaxf(mr0, rmax0), mn1 = fmaxf(mr1, rmax1);
        float al0 = ex2(mr0 - mn0);
        float al1 = ex2(mr1 - mn1);

        float rs0 = 0.f, rs1 = 0.f;
#pragma unroll
        for (int nt = 0; nt < 8; nt++) {
            S[nt][0] = ex2(S[nt][0] - mn0);
            S[nt][1] = ex2(S[nt][1] - mn0);
            S[nt][2] = ex2(S[nt][2] - mn1);
            S[nt][3] = ex2(S[nt][3] - mn1);
            rs0 += S[nt][0] + S[nt][1];
            rs1 += S[nt][2] + S[nt][3];
        }
        rs0 += __shfl_xor_sync(0xffffffffu, rs0, 1);
        rs0 += __shfl_xor_sync(0xffffffffu, rs0, 2);
        rs1 += __shfl_xor_sync(0xffffffffu, rs1, 1);
        rs1 += __shfl_xor_sync(0xffffffffu, rs1, 2);

        l0 = l0 * al0 + rs0;  l1 = l1 * al1 + rs1;
        mr0 = mn0;            mr1 = mn1;
#pragma unroll
        for (int nt = 0; nt < 8; nt++) {
            O_[nt][0] *= al0; O_[nt][1] *= al0;
            O_[nt][2] *= al1; O_[nt][3] *= al1;
        }

        unsigned pf[4][4];
#pragma unroll
        for (int ks = 0; ks < 4; ks++) {
            pf[ks][0] = packbf(S[2 * ks][0],     S[2 * ks][1]);
            pf[ks][1] = packbf(S[2 * ks][2],     S[2 * ks][3]);
            pf[ks][2] = packbf(S[2 * ks + 1][0], S[2 * ks + 1][1]);
            pf[ks][3] = packbf(S[2 * ks + 1][2], S[2 * ks + 1][3]);
        }

#pragma unroll
        for (int ks = 0; ks < 4; ks++) {
#pragma unroll
            for (int dp = 0; dp < 4; dp++) {
                unsigned b0, b1, b2, b3;
                unsigned addr = vs_u + ((dp * 16 + v_row) * KSTR + ks * 16 + v_col) * 2;
                ldsm_x4(b0, b1, b2, b3, addr);
                mma_bf16(O_[2 * dp],     pf[ks][0], pf[ks][1], pf[ks][2], pf[ks][3], b0, b2);
                mma_bf16(O_[2 * dp + 1], pf[ks][0], pf[ks][1], pf[ks][2], pf[ks][3], b1, b3);
            }
        }
    }

    __syncthreads();
    const int g = lane >> 2, qt = lane & 3;
    float inv0 = 1.f / l0, inv1 = 1.f / l1;
#pragma unroll
    for (int dt = 0; dt < 8; dt++) {
        stage[(w16 + g)     * 65 + dt * 8 + 2 * qt]     = O_[dt][0] * inv0;
        stage[(w16 + g)     * 65 + dt * 8 + 2 * qt + 1] = O_[dt][1] * inv0;
        stage[(w16 + g + 8) * 65 + dt * 8 + 2 * qt]     = O_[dt][2] * inv1;
        stage[(w16 + g + 8) * 65 + dt * 8 + 2 * qt + 1] = O_[dt][3] * inv1;
    }
    __syncthreads();

    float* ob = Out + ((size_t)(b * HEADS + h) * HEAD_DIM) * NPTS + n0;
#pragma unroll
    for (int r = 0; r < 32; r++) {
        int idx = r * 256 + t;
        int d = idx >> 7, nn = idx & 127;
        ob[(size_t)d * NPTS + nn] = stage[nn * 65 + d];
    }
}

// ---------------------------------------------------------------------------
// BN stats -> per-channel affine (scale, shift); biased variance like torch.
// ---------------------------------------------------------------------------
__global__ void __launch_bounds__(256) bn_stats_kernel(
    const float* __restrict__ hbuf, const float* __restrict__ gamma,
    const float* __restrict__ beta,
    float* __restrict__ scalep, float* __restrict__ shiftp)
{
    const int c = blockIdx.x;
    float s = 0.f, s2 = 0.f;
    for (int idx = threadIdx.x; idx < NB * NPTS; idx += 256) {
        int b = idx >> 12;
        int n = idx & (NPTS - 1);
        float v = hbuf[((size_t)b * TWO_D + c) * NPTS + n];
        s += v; s2 += v * v;
    }
    __shared__ float sh[256], sh2[256];
    sh[threadIdx.x] = s; sh2[threadIdx.x] = s2;
    __syncthreads();
    for (int st = 128; st > 0; st >>= 1) {
        if (threadIdx.x < st) {
            sh[threadIdx.x]  += sh[threadIdx.x + st];
            sh2[threadIdx.x] += sh2[threadIdx.x + st];
        }
        __syncthreads();
    }
    if (threadIdx.x == 0) {
        const float invn = 1.f / (float)(NB * NPTS);
        float mean = sh[0] * invn;
        float var  = sh2[0] * invn - mean * mean;
        float istd = rsqrtf(var + 1e-5f);
        float sc = gamma[c] * istd;
        scalep[c] = sc;
        shiftp[c] = beta[c] - mean * sc;
    }
}

// ---------------------------------------------------------------------------
extern "C" void kernel_launch(void* const* d_in, const int* in_sizes, int n_in,
                              void* d_out, int out_size)
{
    (void)in_sizes; (void)n_in; (void)out_size;

    const float* x       = (const float*)d_in[0];
    const float* src     = (const float*)d_in[1];
    const float* pq_w    = (const float*)d_in[2];
    const float* pq_b    = (const float*)d_in[3];
    const float* pk_w    = (const float*)d_in[4];
    const float* pk_b    = (const float*)d_in[5];
    const float* pv_w    = (const float*)d_in[6];
    const float* pv_b    = (const float*)d_in[7];
    const float* merge_w = (const float*)d_in[8];
    const float* merge_b = (const float*)d_in[9];
    const float* mlp1_w  = (const float*)d_in[10];
    const float* mlp1_b  = (const float*)d_in[11];
    const float* bn_g    = (const float*)d_in[12];
    const float* bn_b    = (const float*)d_in[13];
    const float* mlp2_w  = (const float*)d_in[14];
    const float* mlp2_b  = (const float*)d_in[15];
    float* out = (float*)d_out;

    float *Qp, *Kp, *Vp, *Ap, *Mp, *Hp, *scalep, *shiftp;
    cudaGetSymbolAddress((void**)&Qp,     g_Q);
    cudaGetSymbolAddress((void**)&Kp,     g_K);
    cudaGetSymbolAddress((void**)&Vp,     g_V);
    cudaGetSymbolAddress((void**)&Ap,     g_attn);
    cudaGetSymbolAddress((void**)&Mp,     g_msg);
    cudaGetSymbolAddress((void**)&Hp,     g_h);
    cudaGetSymbolAddress((void**)&scalep, g_scale);
    cudaGetSymbolAddress((void**)&shiftp, g_shift);

    dim3 blk(256);
    dim3 g256(NPTS / 128, D_MODEL / 128, NB);
    dim3 g512(NPTS / 128, TWO_D / 128, NB);

    // Q/K/V projections (fast bf16 — message path, error-attenuated)
    gemm_bf16<<<g256, blk>>>(x,   pq_w, pq_b, Qp, D_MODEL, D_MODEL, 0);
    gemm_bf16<<<g256, blk>>>(src, pk_w, pk_b, Kp, D_MODEL, D_MODEL, 0);
    gemm_bf16<<<g256, blk>>>(src, pv_w, pv_b, Vp, D_MODEL, D_MODEL, 0);

    // multi-head attention
    flash_attn_bf16<<<dim3(NPTS / 128, HEADS, NB), blk>>>(Qp, Kp, Vp, Ap);

    // merge (fast bf16, X rows permuted for [h][d] storage order)
    gemm_bf16<<<g256, blk>>>(Ap, merge_w, merge_b, Mp, D_MODEL, D_MODEL, 1);

    // mlp1 on concat([x, message]) — HIGH PRECISION (x path)
    gemm_bf16_hp<<<g512, blk>>>(x, Mp, mlp1_w, mlp1_b, nullptr, nullptr,
                                Hp, D_MODEL, D_MODEL, TWO_D, 0);

    // BN stats -> affine
    bn_stats_kernel<<<TWO_D, 256>>>(Hp, bn_g, bn_b, scalep, shiftp);

    // mlp2 with fused BN affine + ReLU — HIGH PRECISION
    gemm_bf16_hp<<<g256, blk>>>(Hp, nullptr, mlp2_w, mlp2_b, scalep, shiftp,
                                out, TWO_D, 0, D_MODEL, 1);
}